// round 16
// baseline (speedup 1.0000x reference)
#include <cuda_runtime.h>

#define BATCH 8
#define NBOX 1024
#define NCLS 32
#define MAXOUT 300
#define HORIZON 352
#define NWORDS ((HORIZON / 32) * (HORIZON / 32 + 1) / 2)   // 66
#define NGF 37        // full groups of 8 per merge
#define NGRP 38       // 37*8 + 4 = 300 outputs per merge
#define SCORE_THRF 0.5f
#define IOU_THRF 0.5f

// Scratch (no allocation allowed)
__device__ unsigned long long g_cand[BATCH * NCLS * MAXOUT]; // 600 KB
__device__ unsigned short g_orig[BATCH * NCLS * NBOX];       // 512 KB: sorted pos -> orig idx

__device__ __forceinline__ float decode_score(unsigned int hi) {
    unsigned int ordered = ~hi;
    if (ordered & 0x80000000u) return __uint_as_float(ordered & 0x7FFFFFFFu);
    return __uint_as_float(~ordered);
}

// Bit-exact suppression test vs reference, cheap-gated and division-free in
// the common case (see R15 comments; verified rel_err 0.0).
__device__ __forceinline__ bool sup_test(float4 a, float aa, float4 b, float ab) {
    float yy1 = fmaxf(a.x, b.x);
    float xx1 = fmaxf(a.y, b.y);
    float yy2 = fminf(a.z, b.z);
    float xx2 = fminf(a.w, b.w);
    float ih = __fsub_rn(yy2, yy1);
    float iw = __fsub_rn(xx2, xx1);
    if (fminf(ih, iw) <= 0.0f) return false;               // ~95% of pairs
    float inter = __fmul_rn(ih, iw);
    float denom = __fsub_rn(__fadd_rn(aa, ab), inter);
    if (__fmul_rn(inter, 2.0f) <= denom) return false;     // rare to pass
    return __fdiv_rn(inter, denom) > IOU_THRF;
}

// ---------------------------------------------------------------------------
// Fused sort+NMS kernel — byte-identical to verified R15.
// ---------------------------------------------------------------------------
__global__ void __launch_bounds__(1024, 2) sortnms_kernel(
        const float* __restrict__ boxes, const float* __restrict__ scores) {
    extern __shared__ unsigned long long dsm[];
    unsigned long long* skeyA = dsm;
    unsigned long long* skeyB = dsm + 1024;
    unsigned int* s_rm = (unsigned int*)dsm;               // [11][352] mask words
    float4* sbox = (float4*)((char*)dsm + 18432);
    float* sarea = (float*)((char*)dsm + 34816);

    __shared__ unsigned int s_kb[HORIZON / 32];
    __shared__ int s_cum;
    __shared__ float4 s_cbox[2][32];
    __shared__ float s_carea[2][32];
    __shared__ int s_cnk[2];
    __shared__ int s_kcv[(NBOX - HORIZON + 31) / 32];
    __shared__ int s_wcnt[32], s_woff[32], s_total;

    int tid = threadIdx.x, lane = tid & 31, wid = tid >> 5;
    int b = blockIdx.x >> 5, c = blockIdx.x & 31;

    unsigned long long key;
    {
        float v = scores[((size_t)b * NBOX + tid) * NCLS + c];
        unsigned int bits = (v > SCORE_THRF) ? __float_as_uint(v) : 0xFF800000u;
        unsigned int ordered = (bits & 0x80000000u) ? ~bits : (bits | 0x80000000u);
        key = ((unsigned long long)(~ordered) << 32) | (unsigned int)tid;
    }

    int pp = 0;
    for (int k = 2; k <= NBOX; k <<= 1) {
        bool up = ((tid & k) == 0);
        for (int j = k >> 1; j > 0; j >>= 1) {
            bool takeMin = (((tid & j) == 0) == up);
            unsigned long long p;
            if (j >= 32) {
                unsigned long long* buf = pp ? skeyB : skeyA;
                buf[tid] = key;
                __syncthreads();
                p = buf[tid ^ j];
                pp ^= 1;
            } else {
                p = __shfl_xor_sync(0xffffffffu, key, j);
            }
            key = takeMin ? (key < p ? key : p) : (key > p ? key : p);
        }
    }

    int n = (int)(key & 0xFFFFFFFFu);
    bool valid = ((unsigned int)(key >> 32) != 0xFF800000u);
    g_orig[(size_t)blockIdx.x * NBOX + tid] = (unsigned short)n;

    float4 bx = ((const float4*)boxes)[(size_t)b * NBOX + n];
    float area = __fmul_rn(__fsub_rn(bx.z, bx.x), __fsub_rn(bx.w, bx.y));
    sbox[tid] = bx;
    sarea[tid] = area;
    int nvalid = __syncthreads_count(valid);
    bool kept;

    for (int widx = wid; widx < NWORDS; widx += 32) {
        int rb = (int)((sqrtf((float)(8 * widx + 1)) - 1.0f) * 0.5f);
        if ((rb + 1) * (rb + 2) / 2 <= widx) rb++;
        if (rb * (rb + 1) / 2 > widx) rb--;
        int wd = widx - rb * (rb + 1) / 2;
        int row = 32 * rb + lane;
        float4 rbx = sbox[row];
        float rar = sarea[row];
        unsigned int m = 0;
        int base = wd * 32;
        #pragma unroll 4
        for (int kk = 0; kk < 32; kk++) {
            int col = base + kk;
            if (sup_test(sbox[col], sarea[col], rbx, rar)) m |= (1u << kk);
        }
        if (wd == rb) m &= (1u << lane) - 1u;
        s_rm[wd * HORIZON + row] = m;
    }
    __syncthreads();

    if (wid == 0) {
        int cum = 0;
        for (int ch = 0; ch < HORIZON / 32; ch++) {
            int row = 32 * ch + lane;
            bool k = (row < nvalid);
            unsigned int sup = 0;
            for (int w2 = 0; w2 < ch; w2++)
                sup |= s_rm[w2 * HORIZON + row] & s_kb[w2];
            if (sup) k = false;
            unsigned int rowmask = s_rm[ch * HORIZON + row];
            unsigned int um = __reduce_or_sync(0xffffffffu, rowmask);
            while (um) {
                int t = __ffs(um) - 1;
                um &= um - 1;
                unsigned int bal = __ballot_sync(0xffffffffu, k);
                if (((bal >> t) & 1u) && ((rowmask >> t) & 1u)) k = false;
            }
            unsigned int ck = __ballot_sync(0xffffffffu, k);
            if (lane == 0) s_kb[ch] = ck;
            cum += __popc(ck);
        }
        if (lane == 0) s_cum = cum;
    }
    __syncthreads();

    int cum = s_cum;
    bool need_fb = (cum < MAXOUT) && (nvalid > HORIZON);
    if (tid < HORIZON) kept = (s_kb[tid >> 5] >> lane) & 1u;
    else               kept = valid && need_fb;

    if (need_fb) {
        __syncthreads();
        float4* fbx = (float4*)dsm;
        float* fba = (float*)(dsm + 1024);
        if (tid < HORIZON && kept) {
            int pre = 0;
            for (int w2 = 0; w2 < (tid >> 5); w2++) pre += __popc(s_kb[w2]);
            int r = pre + __popc(s_kb[tid >> 5] & ((1u << lane) - 1u));
            fbx[r] = bx;
            fba[r] = area;
        }
        __syncthreads();
        if (tid >= HORIZON && kept) {
            bool sup = false;
            #pragma unroll 2
            for (int t = 0; t < cum; t++)
                sup |= sup_test(fbx[t], fba[t], bx, area);
            if (sup) kept = false;
        }
        __syncthreads();
        for (int cb = HORIZON; cb < nvalid; cb += 32) {
            int wc = cb >> 5, buf = wc & 1;
            if (wid == wc) {
                bool k = kept;
                unsigned int rowmask = 0;
                if (k) {
                    for (int t = 0; t < lane; t++)
                        if (sup_test(sbox[cb + t], sarea[cb + t], bx, area))
                            rowmask |= (1u << t);
                }
                unsigned int um = __reduce_or_sync(0xffffffffu, rowmask);
                while (um) {
                    int t = __ffs(um) - 1;
                    um &= um - 1;
                    unsigned int bal = __ballot_sync(0xffffffffu, k);
                    if (((bal >> t) & 1u) && ((rowmask >> t) & 1u)) k = false;
                }
                kept = k;
                unsigned int ck = __ballot_sync(0xffffffffu, k);
                int nk = __popc(ck);
                int ki = __popc(ck & ((1u << lane) - 1u));
                if (k) { s_cbox[buf][ki] = bx; s_carea[buf][ki] = area; }
                if (lane == 0) {
                    s_cnk[buf] = nk;
                    int prev = (wc == HORIZON / 32) ? cum : s_kcv[wc - 1 - HORIZON / 32];
                    s_kcv[wc - HORIZON / 32] = prev + nk;
                }
            }
            __syncthreads();
            if (s_kcv[wc - HORIZON / 32] >= MAXOUT) break;
            if (wid > wc && kept) {
                int nk = s_cnk[buf];
                bool sup = false;
                #pragma unroll 2
                for (int t = 0; t < nk; t++)
                    sup |= sup_test(s_cbox[buf][t], s_carea[buf][t], bx, area);
                if (sup) kept = false;
            }
        }
        __syncthreads();
    }

    unsigned int mask = __ballot_sync(0xffffffffu, kept);
    if (lane == 0) s_wcnt[wid] = __popc(mask);
    __syncthreads();
    if (tid == 0) {
        int acc = 0;
        for (int w = 0; w < 32; w++) { s_woff[w] = acc; acc += s_wcnt[w]; }
        s_total = acc;
    }
    __syncthreads();
    int rank = s_woff[wid] + __popc(mask & ((1u << lane) - 1u));

    unsigned long long* cp = g_cand + (size_t)blockIdx.x * MAXOUT;
    if (kept && rank < MAXOUT) {
        cp[rank] = (key & 0xFFFFFFFF00000000ull) | (unsigned int)(c * NBOX + tid);
    }
    int total = s_total;
    if (tid >= total && tid < MAXOUT) cp[tid] = 0xFFFFFFFFFFFFFFFFull; // pad
}

// ---------------------------------------------------------------------------
// Kernel 2: per-batch global top-300 via truncated merge-path tree. Group
// merge by Batcher half-cleaner: for ascending windows A[0..m-1], B[0..m-1]
// starting at the merge-path split, the m smallest of the 2m elements are
// {min(A[i], B[m-1-i])} — a bitonic sequence, sorted by a static network
// (j=m/2..1). All register accesses statically indexed: no LMEM, no
// dependent pointer-chase. Window reads bounded by off+m-1 <= 299.
// Then dedup by original box index, output compaction, zero padding.
// ---------------------------------------------------------------------------
__global__ void __launch_bounds__(1024) topk_kernel(
        const float* __restrict__ boxes, float* __restrict__ out) {
    extern __shared__ unsigned long long sm[]; // A: 9600 + B: 4800 keys
    unsigned long long* A = sm;
    unsigned long long* Bb = sm + NCLS * MAXOUT;
    __shared__ int s_first[NBOX];
    __shared__ int s_wcnt[32], s_woff[32];
    __shared__ int s_np;

    int b = blockIdx.x;
    int tid = threadIdx.x; // 1024 threads

    const unsigned long long* cp = g_cand + (size_t)b * NCLS * MAXOUT;
    for (int i = tid; i < NCLS * MAXOUT; i += blockDim.x) A[i] = cp[i];
    for (int i = tid; i < NBOX; i += blockDim.x) s_first[i] = 0x7FFFFFFF;
    __syncthreads();

    unsigned long long* src = A;
    unsigned long long* dst = Bb;
    int nl = NCLS;
    while (nl > 1) {
        int ngroups = (nl >> 1) * NGRP;
        for (int p = tid; p < ngroups; p += 1024) {
            int m = p / NGRP, g = p % NGRP;
            const unsigned long long* La = src + (size_t)(2 * m) * MAXOUT;
            const unsigned long long* Lb = La + MAXOUT;
            unsigned long long* D = dst + (size_t)m * MAXOUT;
            if (g < NGF) {
                int off = g * 8;
                int lo = 0, hi = off;
                while (lo < hi) {
                    int a = (lo + hi) >> 1;
                    if (La[a] < Lb[off - 1 - a]) lo = a + 1; else hi = a;
                }
                int a = lo, bi = off - lo;
                unsigned long long W[8], V[8];
                #pragma unroll
                for (int i = 0; i < 8; i++) W[i] = La[a + i];
                #pragma unroll
                for (int i = 0; i < 8; i++) V[i] = Lb[bi + 7 - i]; // reversed
                #pragma unroll
                for (int i = 0; i < 8; i++) W[i] = W[i] < V[i] ? W[i] : V[i];
                // bitonic merge network on bitonic W[0..7]
                #pragma unroll
                for (int j = 4; j >= 1; j >>= 1) {
                    #pragma unroll
                    for (int i = 0; i < 8; i++) {
                        if ((i & j) == 0) {
                            unsigned long long x = W[i], y = W[i | j];
                            W[i] = x < y ? x : y;
                            W[i | j] = x < y ? y : x;
                        }
                    }
                }
                #pragma unroll
                for (int i = 0; i < 8; i++) D[off + i] = W[i];
            } else {
                // tail group: outputs 296..299 (size 4)
                int off = NGF * 8; // 296
                int lo = 0, hi = off;
                while (lo < hi) {
                    int a = (lo + hi) >> 1;
                    if (La[a] < Lb[off - 1 - a]) lo = a + 1; else hi = a;
                }
                int a = lo, bi = off - lo;
                unsigned long long W[4], V[4];
                #pragma unroll
                for (int i = 0; i < 4; i++) W[i] = La[a + i];
                #pragma unroll
                for (int i = 0; i < 4; i++) V[i] = Lb[bi + 3 - i];
                #pragma unroll
                for (int i = 0; i < 4; i++) W[i] = W[i] < V[i] ? W[i] : V[i];
                #pragma unroll
                for (int j = 2; j >= 1; j >>= 1) {
                    #pragma unroll
                    for (int i = 0; i < 4; i++) {
                        if ((i & j) == 0) {
                            unsigned long long x = W[i], y = W[i | j];
                            W[i] = x < y ? x : y;
                            W[i | j] = x < y ? y : x;
                        }
                    }
                }
                #pragma unroll
                for (int i = 0; i < 4; i++) D[off + i] = W[i];
            }
        }
        __syncthreads();
        unsigned long long* t = src; src = dst; dst = t;
        nl >>= 1;
    }
    const unsigned long long* T = src; // top-300, key-ascending = score-descending

    if (tid < MAXOUT) {
        unsigned long long k64 = T[tid];
        float sc = decode_score((unsigned int)(k64 >> 32));
        if (sc > SCORE_THRF) { // padding decodes invalid -> skipped
            int flat = (int)(k64 & 0xFFFFFFFFu);
            int cc = flat >> 10, pos = flat & 1023;
            int orig = (int)g_orig[((size_t)b * NCLS + cc) * NBOX + pos];
            atomicMin(&s_first[orig], tid);
        }
    }
    __syncthreads();

    bool present = (s_first[tid] < 0x7FFFFFFF);
    int lane = tid & 31, wid = tid >> 5;
    unsigned int mask = __ballot_sync(0xffffffffu, present);
    if (lane == 0) s_wcnt[wid] = __popc(mask);
    __syncthreads();
    if (tid == 0) {
        int acc = 0;
        for (int w = 0; w < 32; w++) { s_woff[w] = acc; acc += s_wcnt[w]; }
        s_np = acc;
    }
    __syncthreads();
    int row = s_woff[wid] + __popc(mask & ((1u << lane) - 1u));

    float* ob = out;                              // [8,300,4]
    float* os = out + (size_t)BATCH * MAXOUT * 4; // [8,300]
    float* oc = os + (size_t)BATCH * MAXOUT;      // [8,300] classes as float

    if (present) {
        int p = s_first[tid];
        unsigned long long k64 = T[p];
        float sc = decode_score((unsigned int)(k64 >> 32));
        int flat = (int)(k64 & 0xFFFFFFFFu);
        int cc = flat >> 10;
        float4 bxv = ((const float4*)boxes)[(size_t)b * NBOX + tid];
        ((float4*)ob)[(size_t)b * MAXOUT + row] = bxv;
        os[(size_t)b * MAXOUT + row] = sc;
        oc[(size_t)b * MAXOUT + row] = (float)cc;
    }
    int np = s_np;
    if (tid >= np && tid < MAXOUT) {
        ((float4*)ob)[(size_t)b * MAXOUT + tid] = make_float4(0.f, 0.f, 0.f, 0.f);
        os[(size_t)b * MAXOUT + tid] = 0.f;
        oc[(size_t)b * MAXOUT + tid] = 0.f;
    }
}

// ---------------------------------------------------------------------------
extern "C" void kernel_launch(void* const* d_in, const int* in_sizes, int n_in,
                              void* d_out, int out_size) {
    const float* boxes  = (const float*)d_in[0];
    const float* scores = (const float*)d_in[1];
    if (n_in >= 2 && in_sizes[0] == BATCH * NBOX * NCLS && in_sizes[1] == BATCH * NBOX * 4) {
        scores = (const float*)d_in[0];
        boxes  = (const float*)d_in[1];
    }
    float* out = (float*)d_out;

    size_t nms_smem = 38912; // sort buffers/mask(18KB) + sbox(16KB) + sarea(4KB)
    cudaFuncSetAttribute(sortnms_kernel, cudaFuncAttributeMaxDynamicSharedMemorySize, (int)nms_smem);
    size_t topk_smem = (size_t)(NCLS * MAXOUT + (NCLS / 2) * MAXOUT) * sizeof(unsigned long long);
    cudaFuncSetAttribute(topk_kernel, cudaFuncAttributeMaxDynamicSharedMemorySize, (int)topk_smem);

    sortnms_kernel<<<BATCH * NCLS, NBOX, nms_smem>>>(boxes, scores);
    topk_kernel<<<BATCH, NBOX, topk_smem>>>(boxes, out);
}

// round 17
// speedup vs baseline: 1.0108x; 1.0108x over previous
#include <cuda_runtime.h>

#define BATCH 8
#define NBOX 1024
#define NCLS 32
#define MAXOUT 300
#define HORIZON 352
#define NWORDS ((HORIZON / 32) * (HORIZON / 32 + 1) / 2)   // 66
#define MG 10                                              // merge group size
#define SCORE_THRF 0.5f
#define IOU_THRF 0.5f

// Scratch (no allocation allowed)
__device__ unsigned long long g_cand[BATCH * NCLS * MAXOUT]; // 600 KB
__device__ unsigned short g_orig[BATCH * NCLS * NBOX];       // 512 KB: sorted pos -> orig idx

__device__ __forceinline__ float decode_score(unsigned int hi) {
    unsigned int ordered = ~hi;
    if (ordered & 0x80000000u) return __uint_as_float(ordered & 0x7FFFFFFFu);
    return __uint_as_float(~ordered);
}

// Bit-exact suppression test vs reference, cheap-gated and division-free in
// the common case (verified rel_err 0.0 across rounds).
__device__ __forceinline__ bool sup_test(float4 a, float aa, float4 b, float ab) {
    float yy1 = fmaxf(a.x, b.x);
    float xx1 = fmaxf(a.y, b.y);
    float yy2 = fminf(a.z, b.z);
    float xx2 = fminf(a.w, b.w);
    float ih = __fsub_rn(yy2, yy1);
    float iw = __fsub_rn(xx2, xx1);
    if (fminf(ih, iw) <= 0.0f) return false;               // ~95% of pairs
    float inter = __fmul_rn(ih, iw);
    float denom = __fsub_rn(__fadd_rn(aa, ab), inter);
    if (__fmul_rn(inter, 2.0f) <= denom) return false;     // rare to pass
    return __fdiv_rn(inter, denom) > IOU_THRF;
}

// Empty kernel used only to shift ncu's -s 5 capture onto sortnms_kernel.
__global__ void parity_dummy_kernel() {}

// ---------------------------------------------------------------------------
// Fused sort+NMS kernel — byte-identical to verified R15 (best: 53.3us total).
// ---------------------------------------------------------------------------
__global__ void __launch_bounds__(1024, 2) sortnms_kernel(
        const float* __restrict__ boxes, const float* __restrict__ scores) {
    extern __shared__ unsigned long long dsm[];
    unsigned long long* skeyA = dsm;
    unsigned long long* skeyB = dsm + 1024;
    unsigned int* s_rm = (unsigned int*)dsm;               // [11][352] mask words
    float4* sbox = (float4*)((char*)dsm + 18432);
    float* sarea = (float*)((char*)dsm + 34816);

    __shared__ unsigned int s_kb[HORIZON / 32];
    __shared__ int s_cum;
    __shared__ float4 s_cbox[2][32];
    __shared__ float s_carea[2][32];
    __shared__ int s_cnk[2];
    __shared__ int s_kcv[(NBOX - HORIZON + 31) / 32];
    __shared__ int s_wcnt[32], s_woff[32], s_total;

    int tid = threadIdx.x, lane = tid & 31, wid = tid >> 5;
    int b = blockIdx.x >> 5, c = blockIdx.x & 31;

    unsigned long long key;
    {
        float v = scores[((size_t)b * NBOX + tid) * NCLS + c];
        unsigned int bits = (v > SCORE_THRF) ? __float_as_uint(v) : 0xFF800000u;
        unsigned int ordered = (bits & 0x80000000u) ? ~bits : (bits | 0x80000000u);
        key = ((unsigned long long)(~ordered) << 32) | (unsigned int)tid;
    }

    int pp = 0;
    for (int k = 2; k <= NBOX; k <<= 1) {
        bool up = ((tid & k) == 0);
        for (int j = k >> 1; j > 0; j >>= 1) {
            bool takeMin = (((tid & j) == 0) == up);
            unsigned long long p;
            if (j >= 32) {
                unsigned long long* buf = pp ? skeyB : skeyA;
                buf[tid] = key;
                __syncthreads();
                p = buf[tid ^ j];
                pp ^= 1;
            } else {
                p = __shfl_xor_sync(0xffffffffu, key, j);
            }
            key = takeMin ? (key < p ? key : p) : (key > p ? key : p);
        }
    }

    int n = (int)(key & 0xFFFFFFFFu);
    bool valid = ((unsigned int)(key >> 32) != 0xFF800000u);
    g_orig[(size_t)blockIdx.x * NBOX + tid] = (unsigned short)n;

    float4 bx = ((const float4*)boxes)[(size_t)b * NBOX + n];
    float area = __fmul_rn(__fsub_rn(bx.z, bx.x), __fsub_rn(bx.w, bx.y));
    sbox[tid] = bx;
    sarea[tid] = area;
    int nvalid = __syncthreads_count(valid);
    bool kept;

    for (int widx = wid; widx < NWORDS; widx += 32) {
        int rb = (int)((sqrtf((float)(8 * widx + 1)) - 1.0f) * 0.5f);
        if ((rb + 1) * (rb + 2) / 2 <= widx) rb++;
        if (rb * (rb + 1) / 2 > widx) rb--;
        int wd = widx - rb * (rb + 1) / 2;
        int row = 32 * rb + lane;
        float4 rbx = sbox[row];
        float rar = sarea[row];
        unsigned int m = 0;
        int base = wd * 32;
        #pragma unroll 4
        for (int kk = 0; kk < 32; kk++) {
            int col = base + kk;
            if (sup_test(sbox[col], sarea[col], rbx, rar)) m |= (1u << kk);
        }
        if (wd == rb) m &= (1u << lane) - 1u;
        s_rm[wd * HORIZON + row] = m;
    }
    __syncthreads();

    if (wid == 0) {
        int cum = 0;
        for (int ch = 0; ch < HORIZON / 32; ch++) {
            int row = 32 * ch + lane;
            bool k = (row < nvalid);
            unsigned int sup = 0;
            for (int w2 = 0; w2 < ch; w2++)
                sup |= s_rm[w2 * HORIZON + row] & s_kb[w2];
            if (sup) k = false;
            unsigned int rowmask = s_rm[ch * HORIZON + row];
            unsigned int um = __reduce_or_sync(0xffffffffu, rowmask);
            while (um) {
                int t = __ffs(um) - 1;
                um &= um - 1;
                unsigned int bal = __ballot_sync(0xffffffffu, k);
                if (((bal >> t) & 1u) && ((rowmask >> t) & 1u)) k = false;
            }
            unsigned int ck = __ballot_sync(0xffffffffu, k);
            if (lane == 0) s_kb[ch] = ck;
            cum += __popc(ck);
        }
        if (lane == 0) s_cum = cum;
    }
    __syncthreads();

    int cum = s_cum;
    bool need_fb = (cum < MAXOUT) && (nvalid > HORIZON);
    if (tid < HORIZON) kept = (s_kb[tid >> 5] >> lane) & 1u;
    else               kept = valid && need_fb;

    if (need_fb) {
        __syncthreads();
        float4* fbx = (float4*)dsm;
        float* fba = (float*)(dsm + 1024);
        if (tid < HORIZON && kept) {
            int pre = 0;
            for (int w2 = 0; w2 < (tid >> 5); w2++) pre += __popc(s_kb[w2]);
            int r = pre + __popc(s_kb[tid >> 5] & ((1u << lane) - 1u));
            fbx[r] = bx;
            fba[r] = area;
        }
        __syncthreads();
        if (tid >= HORIZON && kept) {
            bool sup = false;
            #pragma unroll 2
            for (int t = 0; t < cum; t++)
                sup |= sup_test(fbx[t], fba[t], bx, area);
            if (sup) kept = false;
        }
        __syncthreads();
        for (int cb = HORIZON; cb < nvalid; cb += 32) {
            int wc = cb >> 5, buf = wc & 1;
            if (wid == wc) {
                bool k = kept;
                unsigned int rowmask = 0;
                if (k) {
                    for (int t = 0; t < lane; t++)
                        if (sup_test(sbox[cb + t], sarea[cb + t], bx, area))
                            rowmask |= (1u << t);
                }
                unsigned int um = __reduce_or_sync(0xffffffffu, rowmask);
                while (um) {
                    int t = __ffs(um) - 1;
                    um &= um - 1;
                    unsigned int bal = __ballot_sync(0xffffffffu, k);
                    if (((bal >> t) & 1u) && ((rowmask >> t) & 1u)) k = false;
                }
                kept = k;
                unsigned int ck = __ballot_sync(0xffffffffu, k);
                int nk = __popc(ck);
                int ki = __popc(ck & ((1u << lane) - 1u));
                if (k) { s_cbox[buf][ki] = bx; s_carea[buf][ki] = area; }
                if (lane == 0) {
                    s_cnk[buf] = nk;
                    int prev = (wc == HORIZON / 32) ? cum : s_kcv[wc - 1 - HORIZON / 32];
                    s_kcv[wc - HORIZON / 32] = prev + nk;
                }
            }
            __syncthreads();
            if (s_kcv[wc - HORIZON / 32] >= MAXOUT) break;
            if (wid > wc && kept) {
                int nk = s_cnk[buf];
                bool sup = false;
                #pragma unroll 2
                for (int t = 0; t < nk; t++)
                    sup |= sup_test(s_cbox[buf][t], s_carea[buf][t], bx, area);
                if (sup) kept = false;
            }
        }
        __syncthreads();
    }

    unsigned int mask = __ballot_sync(0xffffffffu, kept);
    if (lane == 0) s_wcnt[wid] = __popc(mask);
    __syncthreads();
    if (tid == 0) {
        int acc = 0;
        for (int w = 0; w < 32; w++) { s_woff[w] = acc; acc += s_wcnt[w]; }
        s_total = acc;
    }
    __syncthreads();
    int rank = s_woff[wid] + __popc(mask & ((1u << lane) - 1u));

    unsigned long long* cp = g_cand + (size_t)blockIdx.x * MAXOUT;
    if (kept && rank < MAXOUT) {
        cp[rank] = (key & 0xFFFFFFFF00000000ull) | (unsigned int)(c * NBOX + tid);
    }
    int total = s_total;
    if (tid >= total && tid < MAXOUT) cp[tid] = 0xFFFFFFFFFFFFFFFFull; // pad
}

// ---------------------------------------------------------------------------
// Kernel 2: per-batch global top-300 via truncated merge-path tree with
// GROUP-GRANULARITY merging (verbatim verified R12 version, 14.0us best).
// ---------------------------------------------------------------------------
__global__ void topk_kernel(const float* __restrict__ boxes, float* __restrict__ out) {
    extern __shared__ unsigned long long sm[]; // A: 9600 + B: 4800 keys
    unsigned long long* A = sm;
    unsigned long long* Bb = sm + NCLS * MAXOUT;
    __shared__ int s_first[NBOX];
    __shared__ int s_wcnt[32], s_woff[32];
    __shared__ int s_np;

    int b = blockIdx.x;
    int tid = threadIdx.x; // 1024 threads

    const unsigned long long* cp = g_cand + (size_t)b * NCLS * MAXOUT;
    for (int i = tid; i < NCLS * MAXOUT; i += blockDim.x) A[i] = cp[i];
    for (int i = tid; i < NBOX; i += blockDim.x) s_first[i] = 0x7FFFFFFF;
    __syncthreads();

    unsigned long long* src = A;
    unsigned long long* dst = Bb;
    int nl = NCLS;
    while (nl > 1) {
        int ngroups = (nl >> 1) * (MAXOUT / MG);
        for (int p = tid; p < ngroups; p += 1024) {
            int m = p / (MAXOUT / MG);
            int g = p % (MAXOUT / MG);
            int off = g * MG;
            const unsigned long long* La = src + (size_t)(2 * m) * MAXOUT;
            const unsigned long long* Lb = La + MAXOUT;
            int lo = 0, hi = off;
            while (lo < hi) {
                int a = (lo + hi) >> 1;
                if (La[a] < Lb[off - 1 - a]) lo = a + 1; else hi = a;
            }
            int a = lo, bi = off - lo;
            unsigned long long* D = dst + (size_t)m * MAXOUT + off;
            #pragma unroll
            for (int i = 0; i < MG; i++) {
                unsigned long long va = La[a], vb = Lb[bi];
                bool ta = va < vb;
                D[i] = ta ? va : vb;
                if (ta) a++; else bi++;
            }
        }
        __syncthreads();
        unsigned long long* t = src; src = dst; dst = t;
        nl >>= 1;
    }
    const unsigned long long* T = src; // top-300, key-ascending = score-descending

    if (tid < MAXOUT) {
        unsigned long long k64 = T[tid];
        float sc = decode_score((unsigned int)(k64 >> 32));
        if (sc > SCORE_THRF) {
            int flat = (int)(k64 & 0xFFFFFFFFu);
            int cc = flat >> 10, pos = flat & 1023;
            int orig = (int)g_orig[((size_t)b * NCLS + cc) * NBOX + pos];
            atomicMin(&s_first[orig], tid);
        }
    }
    __syncthreads();

    bool present = (s_first[tid] < 0x7FFFFFFF);
    int lane = tid & 31, wid = tid >> 5;
    unsigned int mask = __ballot_sync(0xffffffffu, present);
    if (lane == 0) s_wcnt[wid] = __popc(mask);
    __syncthreads();
    if (tid == 0) {
        int acc = 0;
        for (int w = 0; w < 32; w++) { s_woff[w] = acc; acc += s_wcnt[w]; }
        s_np = acc;
    }
    __syncthreads();
    int row = s_woff[wid] + __popc(mask & ((1u << lane) - 1u));

    float* ob = out;                              // [8,300,4]
    float* os = out + (size_t)BATCH * MAXOUT * 4; // [8,300]
    float* oc = os + (size_t)BATCH * MAXOUT;      // [8,300] classes as float

    if (present) {
        int p = s_first[tid];
        unsigned long long k64 = T[p];
        float sc = decode_score((unsigned int)(k64 >> 32));
        int flat = (int)(k64 & 0xFFFFFFFFu);
        int cc = flat >> 10;
        float4 bxv = ((const float4*)boxes)[(size_t)b * NBOX + tid];
        ((float4*)ob)[(size_t)b * MAXOUT + row] = bxv;
        os[(size_t)b * MAXOUT + row] = sc;
        oc[(size_t)b * MAXOUT + row] = (float)cc;
    }
    int np = s_np;
    if (tid >= np && tid < MAXOUT) {
        ((float4*)ob)[(size_t)b * MAXOUT + tid] = make_float4(0.f, 0.f, 0.f, 0.f);
        os[(size_t)b * MAXOUT + tid] = 0.f;
        oc[(size_t)b * MAXOUT + tid] = 0.f;
    }
}

// ---------------------------------------------------------------------------
// Launch order [dummy, sortnms, topk, dummy]: period-4 sequence puts global
// launch index 5 (ncu -s 5 -c 1) on sortnms_kernel — first real profile of
// the dominant kernel. Dummies are empty; deterministic; graph-capturable.
// ---------------------------------------------------------------------------
extern "C" void kernel_launch(void* const* d_in, const int* in_sizes, int n_in,
                              void* d_out, int out_size) {
    const float* boxes  = (const float*)d_in[0];
    const float* scores = (const float*)d_in[1];
    if (n_in >= 2 && in_sizes[0] == BATCH * NBOX * NCLS && in_sizes[1] == BATCH * NBOX * 4) {
        scores = (const float*)d_in[0];
        boxes  = (const float*)d_in[1];
    }
    float* out = (float*)d_out;

    size_t nms_smem = 38912; // sort buffers/mask(18KB) + sbox(16KB) + sarea(4KB)
    cudaFuncSetAttribute(sortnms_kernel, cudaFuncAttributeMaxDynamicSharedMemorySize, (int)nms_smem);
    size_t topk_smem = (size_t)(NCLS * MAXOUT + (NCLS / 2) * MAXOUT) * sizeof(unsigned long long);
    cudaFuncSetAttribute(topk_kernel, cudaFuncAttributeMaxDynamicSharedMemorySize, (int)topk_smem);

    parity_dummy_kernel<<<1, 32>>>();
    sortnms_kernel<<<BATCH * NCLS, NBOX, nms_smem>>>(boxes, scores);
    topk_kernel<<<BATCH, NBOX, topk_smem>>>(boxes, out);
    parity_dummy_kernel<<<1, 32>>>();
}